// round 13
// baseline (speedup 1.0000x reference)
#include <cuda_runtime.h>
#include <math.h>

#define BB 512
#define NN 120
#define DD 64
#define ROWS (BB*NN)           // 61440
#define NBINS 32

typedef unsigned long long u64;

// ---------------- scratch (static device arrays; no cudaMalloc) ----------------
__device__ float  g_q[ROWS*DD];
__device__ float  g_k[ROWS*DD];
__device__ float  g_v[ROWS*DD];
__device__ float  g_gam[ROWS];
__device__ float  g_o[ROWS*DD];
// packed twiddles: twp[d2*32+f] = (cos(w*f*2d2), cos(w*f*(2d2+1)), sin(...), sin(...))
__device__ float4 g_twp[1024];
// W repacked over e-pairs: P[e2*32+lane] = (W[2e2][2l], W[2e2+1][2l], W[2e2][2l+1], W[2e2+1][2l+1])
__device__ float4 g_Wqp[1024], g_Wkp[1024], g_Wvp[1024], g_Wop[1024];

// ---------------- f32x2 helpers ----------------
__device__ __forceinline__ u64 fma2(u64 a, u64 b, u64 c) {
    u64 d; asm("fma.rn.f32x2 %0,%1,%2,%3;" : "=l"(d) : "l"(a), "l"(b), "l"(c)); return d;
}
__device__ __forceinline__ u64 mul2(u64 a, u64 b) {
    u64 d; asm("mul.rn.f32x2 %0,%1,%2;" : "=l"(d) : "l"(a), "l"(b)); return d;
}
__device__ __forceinline__ u64 dup2(float v) {
    u64 r; asm("mov.b64 %0,{%1,%1};" : "=l"(r) : "f"(v)); return r;
}
__device__ __forceinline__ float2 unp(u64 v) {
    float a, b; asm("mov.b64 {%0,%1},%2;" : "=f"(a), "=f"(b) : "l"(v));
    return make_float2(a, b);
}
// S' = clip(g*S + delta*k, +-10)
__device__ __forceinline__ u64 upd2(u64 S, u64 k, u64 g, u64 delta) {
    u64 r;
    asm("{\n\t"
        ".reg .f32 lo,hi;\n\t"
        ".reg .b64 t;\n\t"
        "mul.rn.f32x2 t, %2, %3;\n\t"
        "fma.rn.f32x2 t, %4, %1, t;\n\t"
        "mov.b64 {lo,hi}, t;\n\t"
        "min.f32 lo, lo, 0f41200000;\n\t"
        "max.f32 lo, lo, 0fC1200000;\n\t"
        "min.f32 hi, hi, 0f41200000;\n\t"
        "max.f32 hi, hi, 0fC1200000;\n\t"
        "mov.b64 %0, {lo,hi};\n\t"
        "}"
        : "=l"(r) : "l"(S), "l"(k), "l"(delta), "l"(g));
    return r;
}

// ---------------- init: packed twiddles + W e-pair repack ----------------
__global__ void init_kernel(const float* __restrict__ Wq, const float* __restrict__ Wk,
                            const float* __restrict__ Wv, const float* __restrict__ Wo) {
    int i = blockIdx.x * blockDim.x + threadIdx.x;
    if (i < 1024) {
        int d2 = i >> 5, f = i & 31;
        int m0 = (f * (2*d2))     & 63;       // exact modular angle reduction
        int m1 = (f * (2*d2 + 1)) & 63;
        const double w = 2.0 * 3.14159265358979323846 / 64.0;
        g_twp[i] = make_float4((float)cos(w*m0), (float)cos(w*m1),
                               (float)sin(w*m0), (float)sin(w*m1));
    } else if (i < 5120) {
        int s = (i - 1024) >> 10, j = (i - 1024) & 1023;
        int e2 = j >> 5, l = j & 31;
        const float* W = (s == 0) ? Wq : (s == 1) ? Wk : (s == 2) ? Wv : Wo;
        float4*      P = (s == 0) ? g_Wqp : (s == 1) ? g_Wkp : (s == 2) ? g_Wvp : g_Wop;
        int a = (2*e2)*DD + 2*l;
        P[j] = make_float4(W[a], W[a+DD], W[a+1], W[a+DD+1]);
    }
}

// ---------------- preprocess: 4 rows/warp, combined q/k/v pass ----------------
__global__ void __launch_bounds__(256) pre_kernel(
    const float* __restrict__ x,  const float* __restrict__ g_norm,
    const float* __restrict__ bv,
    const float* __restrict__ W1, const float* __restrict__ b1,
    const float* __restrict__ W2, const float* __restrict__ b2)
{
    const int warp = threadIdx.x >> 5;
    const int lane = threadIdx.x & 31;
    const int row0 = blockIdx.x * 32 + warp * 4;
    __shared__ __align__(16) float sh[8][4][DD];
    __shared__ float smag[8][4][NBINS];

    // ---- zc_rms for 4 rows (variance identity; parallel reductions) ----
    float2 gv = ((const float2*)g_norm)[lane];
    #pragma unroll
    for (int r = 0; r < 4; r++) {
        float2 xv = ((const float2*)(x + (row0 + r)*DD))[lane];
        float s  = xv.x + xv.y;
        float ss = xv.x*xv.x + xv.y*xv.y;
        #pragma unroll
        for (int o = 16; o; o >>= 1) {
            s  += __shfl_xor_sync(0xffffffffu, s,  o);
            ss += __shfl_xor_sync(0xffffffffu, ss, o);
        }
        float mean = s * (1.0f/64.0f);
        float var  = fmaf(-mean, mean, ss * (1.0f/64.0f));
        float rn = rsqrtf(var + 1e-8f);
        sh[warp][r][2*lane]   = (xv.x - mean) * rn * gv.x;
        sh[warp][r][2*lane+1] = (xv.y - mean) * rn * gv.y;
    }
    __syncwarp();

    // ---- three matvecs, packed over e-pairs, one combined pass ----
    u64 qE[4], qO[4], kE[4], kO[4], vE[4], vO[4];
    #pragma unroll
    for (int r = 0; r < 4; r++) { qE[r]=qO[r]=kE[r]=kO[r]=vE[r]=vO[r]=0ull; }
    const ulonglong2* Wqp = (const ulonglong2*)g_Wqp;
    const ulonglong2* Wkp = (const ulonglong2*)g_Wkp;
    const ulonglong2* Wvp = (const ulonglong2*)g_Wvp;
    #pragma unroll 4
    for (int e2 = 0; e2 < 32; e2++) {
        ulonglong2 wq = Wqp[e2*32 + lane];
        ulonglong2 wk = Wkp[e2*32 + lane];
        ulonglong2 wv = Wvp[e2*32 + lane];
        #pragma unroll
        for (int r = 0; r < 4; r++) {
            u64 h2 = ((const u64*)sh[warp][r])[e2];   // (h[2e2], h[2e2+1])
            qE[r] = fma2(h2, wq.x, qE[r]);  qO[r] = fma2(h2, wq.y, qO[r]);
            kE[r] = fma2(h2, wk.x, kE[r]);  kO[r] = fma2(h2, wk.y, kO[r]);
            vE[r] = fma2(h2, wv.x, vE[r]);  vO[r] = fma2(h2, wv.y, vO[r]);
        }
    }
    float2 bvv = ((const float2*)bv)[lane];
    #pragma unroll
    for (int r = 0; r < 4; r++) {
        float2 e0 = unp(qE[r]), e1 = unp(qO[r]);
        float q0 = e0.x + e0.y, q1 = e1.x + e1.y;
        e0 = unp(kE[r]); e1 = unp(kO[r]);
        float k0 = e0.x + e0.y, k1 = e1.x + e1.y;
        e0 = unp(vE[r]); e1 = unp(vO[r]);
        float v0 = e0.x + e0.y, v1 = e1.x + e1.y;

        float qs = q0*q0 + q1*q1;
        float ks = k0*k0 + k1*k1;
        #pragma unroll
        for (int o = 16; o; o >>= 1) {
            qs += __shfl_xor_sync(0xffffffffu, qs, o);
            ks += __shfl_xor_sync(0xffffffffu, ks, o);
        }
        float qr = rsqrtf(qs + 1e-8f);
        float kr = rsqrtf(ks + 1e-8f);
        int row = row0 + r;
        ((float2*)(g_q + row*DD))[lane] = make_float2(q0*qr, q1*qr);
        ((float2*)(g_k + row*DD))[lane] = make_float2(k0*kr, k1*kr);
        ((float2*)(g_v + row*DD))[lane] = make_float2(v0 + bvv.x, v1 + bvv.y);
    }

    // ---- DFT magnitudes, bin = lane, packed twiddles ----
    u64 re2[4] = {0,0,0,0}, im2[4] = {0,0,0,0};
    const ulonglong2* Twp = (const ulonglong2*)g_twp;
    #pragma unroll 4
    for (int d2 = 0; d2 < 32; d2++) {
        ulonglong2 t2 = Twp[d2*32 + lane];    // (cos pair, sin pair)
        #pragma unroll
        for (int r = 0; r < 4; r++) {
            u64 h2 = ((const u64*)sh[warp][r])[d2];
            re2[r] = fma2(h2, t2.x, re2[r]);
            im2[r] = fma2(h2, t2.y, im2[r]);
        }
    }
    #pragma unroll
    for (int r = 0; r < 4; r++) {
        float2 rr = unp(re2[r]), ii = unp(im2[r]);
        float re = rr.x + rr.y, im = ii.x + ii.y;
        smag[warp][r][lane] = sqrtf(re*re + im*im);
    }
    __syncwarp();

    // ---- gate: 8 lanes per row, lane = (row, band) ----
    {
        int r   = lane >> 3;      // row within group of 4
        int bnd = lane & 7;       // band index
        const float* mg = smag[warp][r];
        float en = 0.25f * (mg[4*bnd] + mg[4*bnd+1] + mg[4*bnd+2] + mg[4*bnd+3]);
        float esum = en;
        esum += __shfl_xor_sync(0xffffffffu, esum, 1);
        esum += __shfl_xor_sync(0xffffffffu, esum, 2);
        esum += __shfl_xor_sync(0xffffffffu, esum, 4);
        float eni = en / fmaxf(esum, 1e-8f);
        float z0 = b1[2*bnd], z1 = b1[2*bnd+1];
        int gbase = lane & 24;    // start lane of this 8-lane group
        #pragma unroll
        for (int i = 0; i < 8; i++) {
            float ei = __shfl_sync(0xffffffffu, eni, gbase + i);
            z0 = fmaf(ei, W1[i*16 + 2*bnd],     z0);
            z1 = fmaf(ei, W1[i*16 + 2*bnd + 1], z1);
        }
        float s0 = z0 / (1.0f + expf(-z0)) * W2[2*bnd];
        float s1 = z1 / (1.0f + expf(-z1)) * W2[2*bnd+1];
        float hid = s0 + s1;
        hid += __shfl_xor_sync(0xffffffffu, hid, 1);
        hid += __shfl_xor_sync(0xffffffffu, hid, 2);
        hid += __shfl_xor_sync(0xffffffffu, hid, 4);
        if (bnd == 0) {
            float z2 = hid + b2[0];
            g_gam[row0 + r] = 0.5f + 0.49f / (1.0f + expf(-z2));
        }
    }
}

// ---------------- scan: 4 threads/row, packed state, pointer-walk loads (R7 best) ----------------
// NOTE: idempotent (S starts at 0, writes same g_o) — launched TWICE this round to
// measure its duration as the total-time delta vs R12. Remove the 2nd launch next round.
__global__ void __launch_bounds__(256, 4) scan_kernel() {
    const int b   = blockIdx.x;
    const int d   = threadIdx.x >> 2;
    const int sub = threadIdx.x & 3;

    const ulonglong2* __restrict__ kp = (const ulonglong2*)(g_k + b*NN*DD + sub*16);
    const ulonglong2* __restrict__ qp = (const ulonglong2*)(g_q + b*NN*DD + sub*16);
    const float*  __restrict__ vp = g_v + b*NN*DD + d;
    const float*  __restrict__ gp = g_gam + b*NN;
    float*        __restrict__ op = g_o + b*NN*DD + d;

    u64 S2[8];
    #pragma unroll
    for (int i = 0; i < 8; i++) S2[i] = 0ull;

    #pragma unroll 1
    for (int t = 0; t < NN; t++) {
        ulonglong2 kA = kp[0], kB = kp[1], kC = kp[2], kD = kp[3];
        ulonglong2 qA = qp[0], qB = qp[1], qC = qp[2], qD = qp[3];
        kp += 16; qp += 16;
        float gc = *gp++;
        float vc = *vp; vp += DD;

        u64 k2[8] = {kA.x, kA.y, kB.x, kB.y, kC.x, kC.y, kD.x, kD.y};
        u64 q2[8] = {qA.x, qA.y, qB.x, qB.y, qC.x, qC.y, qD.x, qD.y};

        // pred = S_row . k   (two packed chains, then sub-lane all-reduce)
        u64 pa = mul2(S2[0], k2[0]);
        pa = fma2(S2[1], k2[1], pa);
        pa = fma2(S2[2], k2[2], pa);
        pa = fma2(S2[3], k2[3], pa);
        u64 pb = mul2(S2[4], k2[4]);
        pb = fma2(S2[5], k2[5], pb);
        pb = fma2(S2[6], k2[6], pb);
        pb = fma2(S2[7], k2[7], pb);
        float2 ua = unp(pa), ub = unp(pb);
        float pred = (ua.x + ua.y) + (ub.x + ub.y);
        pred += __shfl_xor_sync(0xffffffffu, pred, 1);
        pred += __shfl_xor_sync(0xffffffffu, pred, 2);

        float delta = fminf(fmaxf(vc - pred, -5.0f), 5.0f);
        u64 g2 = dup2(gc), dl2 = dup2(delta);

        // S = clip(g*S + delta*k); o = S_new . q  (packed)
        u64 oa, ob;
        S2[0] = upd2(S2[0], k2[0], g2, dl2);  oa = mul2(S2[0], q2[0]);
        S2[1] = upd2(S2[1], k2[1], g2, dl2);  oa = fma2(S2[1], q2[1], oa);
        S2[2] = upd2(S2[2], k2[2], g2, dl2);  oa = fma2(S2[2], q2[2], oa);
        S2[3] = upd2(S2[3], k2[3], g2, dl2);  oa = fma2(S2[3], q2[3], oa);
        S2[4] = upd2(S2[4], k2[4], g2, dl2);  ob = mul2(S2[4], q2[4]);
        S2[5] = upd2(S2[5], k2[5], g2, dl2);  ob = fma2(S2[5], q2[5], ob);
        S2[6] = upd2(S2[6], k2[6], g2, dl2);  ob = fma2(S2[6], q2[6], ob);
        S2[7] = upd2(S2[7], k2[7], g2, dl2);  ob = fma2(S2[7], q2[7], ob);

        float2 oa2 = unp(oa), ob2 = unp(ob);
        float o = (oa2.x + oa2.y) + (ob2.x + ob2.y);
        o += __shfl_xor_sync(0xffffffffu, o, 1);
        o += __shfl_xor_sync(0xffffffffu, o, 2);
        if (sub == 0) op[t*DD] = o;
    }
}

// ---------------- epilogue: 4 rows/warp ----------------
__global__ void __launch_bounds__(256) post_kernel(
    const float* __restrict__ x, const float* __restrict__ g_post,
    const float* __restrict__ bo, float* __restrict__ out)
{
    const int warp = threadIdx.x >> 5;
    const int lane = threadIdx.x & 31;
    const int row0 = blockIdx.x * 32 + warp * 4;
    __shared__ __align__(16) float sh[8][4][DD];

    float2 gp2 = ((const float2*)g_post)[lane];
    #pragma unroll
    for (int r = 0; r < 4; r++) {
        float2 ov = ((const float2*)(g_o + (row0 + r)*DD))[lane];
        float s  = ov.x + ov.y;
        float ss = ov.x*ov.x + ov.y*ov.y;
        #pragma unroll
        for (int o = 16; o; o >>= 1) {
            s  += __shfl_xor_sync(0xffffffffu, s,  o);
            ss += __shfl_xor_sync(0xffffffffu, ss, o);
        }
        float mean = s * (1.0f/64.0f);
        float var  = fmaf(-mean, mean, ss * (1.0f/64.0f));
        float rn = rsqrtf(var + 1e-8f);
        sh[warp][r][2*lane]   = (ov.x - mean) * rn * gp2.x;
        sh[warp][r][2*lane+1] = (ov.y - mean) * rn * gp2.y;
    }
    __syncwarp();

    u64 aE[4], aO[4];
    #pragma unroll
    for (int r = 0; r < 4; r++) { aE[r] = aO[r] = 0ull; }
    const ulonglong2* Wop = (const ulonglong2*)g_Wop;
    #pragma unroll 4
    for (int e2 = 0; e2 < 32; e2++) {
        ulonglong2 wo = Wop[e2*32 + lane];
        #pragma unroll
        for (int r = 0; r < 4; r++) {
            u64 h2 = ((const u64*)sh[warp][r])[e2];
            aE[r] = fma2(h2, wo.x, aE[r]);
            aO[r] = fma2(h2, wo.y, aO[r]);
        }
    }
    float2 bov = ((const float2*)bo)[lane];
    #pragma unroll
    for (int r = 0; r < 4; r++) {
        float2 e0 = unp(aE[r]), e1 = unp(aO[r]);
        int row = row0 + r;
        float2 xv = ((const float2*)(x + row*DD))[lane];
        ((float2*)(out + row*DD))[lane] =
            make_float2(xv.x + e0.x + e0.y + bov.x,
                        xv.y + e1.x + e1.y + bov.y);
    }
}

// ---------------- launch ----------------
extern "C" void kernel_launch(void* const* d_in, const int* in_sizes, int n_in,
                              void* d_out, int out_size)
{
    const float* x      = (const float*)d_in[0];
    const float* g_norm = (const float*)d_in[1];
    const float* Wq     = (const float*)d_in[2];
    const float* Wk     = (const float*)d_in[3];
    const float* Wv     = (const float*)d_in[4];
    const float* bv     = (const float*)d_in[5];
    const float* Wo     = (const float*)d_in[6];
    const float* bo     = (const float*)d_in[7];
    const float* g_post = (const float*)d_in[8];
    const float* W1     = (const float*)d_in[9];
    const float* b1     = (const float*)d_in[10];
    const float* W2     = (const float*)d_in[11];
    const float* b2     = (const float*)d_in[12];
    float* out          = (float*)d_out;

    init_kernel<<<20, 256>>>(Wq, Wk, Wv, Wo);
    pre_kernel<<<ROWS/32, 256>>>(x, g_norm, bv, W1, b1, W2, b2);
    scan_kernel<<<BB, 256>>>();
    scan_kernel<<<BB, 256>>>();   // MEASUREMENT: duplicate launch; delta vs R12 = scan duration
    post_kernel<<<ROWS/32, 256>>>(x, g_post, bo, out);
}

// round 14
// speedup vs baseline: 1.9168x; 1.9168x over previous
#include <cuda_runtime.h>
#include <math.h>

#define BB 512
#define NN 120
#define DD 64
#define ROWS (BB*NN)           // 61440
#define NBINS 32

typedef unsigned long long u64;

// ---------------- scratch (static device arrays; no cudaMalloc) ----------------
__device__ float  g_q[ROWS*DD];
__device__ float  g_k[ROWS*DD];
__device__ float  g_v[ROWS*DD];
__device__ float  g_gam[ROWS];
__device__ float  g_o[ROWS*DD];
// packed twiddles: twp[d2*32+f] = (cos(w*f*2d2), cos(w*f*(2d2+1)), sin(...), sin(...))
__device__ float4 g_twp[1024];
// W repacked over e-pairs: P[e2*32+lane] = (W[2e2][2l], W[2e2+1][2l], W[2e2][2l+1], W[2e2+1][2l+1])
__device__ float4 g_Wqp[1024], g_Wkp[1024], g_Wvp[1024], g_Wop[1024];

// ---------------- f32x2 helpers ----------------
__device__ __forceinline__ u64 fma2(u64 a, u64 b, u64 c) {
    u64 d; asm("fma.rn.f32x2 %0,%1,%2,%3;" : "=l"(d) : "l"(a), "l"(b), "l"(c)); return d;
}
__device__ __forceinline__ u64 mul2(u64 a, u64 b) {
    u64 d; asm("mul.rn.f32x2 %0,%1,%2;" : "=l"(d) : "l"(a), "l"(b)); return d;
}
__device__ __forceinline__ u64 dup2(float v) {
    u64 r; asm("mov.b64 %0,{%1,%1};" : "=l"(r) : "f"(v)); return r;
}
__device__ __forceinline__ float2 unp(u64 v) {
    float a, b; asm("mov.b64 {%0,%1},%2;" : "=f"(a), "=f"(b) : "l"(v));
    return make_float2(a, b);
}
// S' = clip(g*S + delta*k, +-10)
__device__ __forceinline__ u64 upd2(u64 S, u64 k, u64 g, u64 delta) {
    u64 r;
    asm("{\n\t"
        ".reg .f32 lo,hi;\n\t"
        ".reg .b64 t;\n\t"
        "mul.rn.f32x2 t, %2, %3;\n\t"
        "fma.rn.f32x2 t, %4, %1, t;\n\t"
        "mov.b64 {lo,hi}, t;\n\t"
        "min.f32 lo, lo, 0f41200000;\n\t"
        "max.f32 lo, lo, 0fC1200000;\n\t"
        "min.f32 hi, hi, 0f41200000;\n\t"
        "max.f32 hi, hi, 0fC1200000;\n\t"
        "mov.b64 %0, {lo,hi};\n\t"
        "}"
        : "=l"(r) : "l"(S), "l"(k), "l"(delta), "l"(g));
    return r;
}

// ---------------- init: packed twiddles + W e-pair repack ----------------
__global__ void init_kernel(const float* __restrict__ Wq, const float* __restrict__ Wk,
                            const float* __restrict__ Wv, const float* __restrict__ Wo) {
    int i = blockIdx.x * blockDim.x + threadIdx.x;
    if (i < 1024) {
        int d2 = i >> 5, f = i & 31;
        int m0 = (f * (2*d2))     & 63;       // exact modular angle reduction
        int m1 = (f * (2*d2 + 1)) & 63;
        const double w = 2.0 * 3.14159265358979323846 / 64.0;
        g_twp[i] = make_float4((float)cos(w*m0), (float)cos(w*m1),
                               (float)sin(w*m0), (float)sin(w*m1));
    } else if (i < 5120) {
        int s = (i - 1024) >> 10, j = (i - 1024) & 1023;
        int e2 = j >> 5, l = j & 31;
        const float* W = (s == 0) ? Wq : (s == 1) ? Wk : (s == 2) ? Wv : Wo;
        float4*      P = (s == 0) ? g_Wqp : (s == 1) ? g_Wkp : (s == 2) ? g_Wvp : g_Wop;
        int a = (2*e2)*DD + 2*l;
        P[j] = make_float4(W[a], W[a+DD], W[a+1], W[a+DD+1]);
    }
}

// ---------------- preprocess: 4 rows/warp, combined q/k/v pass ----------------
__global__ void __launch_bounds__(256) pre_kernel(
    const float* __restrict__ x,  const float* __restrict__ g_norm,
    const float* __restrict__ bv,
    const float* __restrict__ W1, const float* __restrict__ b1,
    const float* __restrict__ W2, const float* __restrict__ b2)
{
    const int warp = threadIdx.x >> 5;
    const int lane = threadIdx.x & 31;
    const int row0 = blockIdx.x * 32 + warp * 4;
    __shared__ __align__(16) float sh[8][4][DD];
    __shared__ float smag[8][4][NBINS];

    // ---- zc_rms for 4 rows (variance identity; parallel reductions) ----
    float2 gv = ((const float2*)g_norm)[lane];
    #pragma unroll
    for (int r = 0; r < 4; r++) {
        float2 xv = ((const float2*)(x + (row0 + r)*DD))[lane];
        float s  = xv.x + xv.y;
        float ss = xv.x*xv.x + xv.y*xv.y;
        #pragma unroll
        for (int o = 16; o; o >>= 1) {
            s  += __shfl_xor_sync(0xffffffffu, s,  o);
            ss += __shfl_xor_sync(0xffffffffu, ss, o);
        }
        float mean = s * (1.0f/64.0f);
        float var  = fmaf(-mean, mean, ss * (1.0f/64.0f));
        float rn = rsqrtf(var + 1e-8f);
        sh[warp][r][2*lane]   = (xv.x - mean) * rn * gv.x;
        sh[warp][r][2*lane+1] = (xv.y - mean) * rn * gv.y;
    }
    __syncwarp();

    // ---- three matvecs, packed over e-pairs, one combined pass ----
    u64 qE[4], qO[4], kE[4], kO[4], vE[4], vO[4];
    #pragma unroll
    for (int r = 0; r < 4; r++) { qE[r]=qO[r]=kE[r]=kO[r]=vE[r]=vO[r]=0ull; }
    const ulonglong2* Wqp = (const ulonglong2*)g_Wqp;
    const ulonglong2* Wkp = (const ulonglong2*)g_Wkp;
    const ulonglong2* Wvp = (const ulonglong2*)g_Wvp;
    #pragma unroll 4
    for (int e2 = 0; e2 < 32; e2++) {
        ulonglong2 wq = Wqp[e2*32 + lane];
        ulonglong2 wk = Wkp[e2*32 + lane];
        ulonglong2 wv = Wvp[e2*32 + lane];
        #pragma unroll
        for (int r = 0; r < 4; r++) {
            u64 h2 = ((const u64*)sh[warp][r])[e2];   // (h[2e2], h[2e2+1])
            qE[r] = fma2(h2, wq.x, qE[r]);  qO[r] = fma2(h2, wq.y, qO[r]);
            kE[r] = fma2(h2, wk.x, kE[r]);  kO[r] = fma2(h2, wk.y, kO[r]);
            vE[r] = fma2(h2, wv.x, vE[r]);  vO[r] = fma2(h2, wv.y, vO[r]);
        }
    }
    float2 bvv = ((const float2*)bv)[lane];
    #pragma unroll
    for (int r = 0; r < 4; r++) {
        float2 e0 = unp(qE[r]), e1 = unp(qO[r]);
        float q0 = e0.x + e0.y, q1 = e1.x + e1.y;
        e0 = unp(kE[r]); e1 = unp(kO[r]);
        float k0 = e0.x + e0.y, k1 = e1.x + e1.y;
        e0 = unp(vE[r]); e1 = unp(vO[r]);
        float v0 = e0.x + e0.y, v1 = e1.x + e1.y;

        float qs = q0*q0 + q1*q1;
        float ks = k0*k0 + k1*k1;
        #pragma unroll
        for (int o = 16; o; o >>= 1) {
            qs += __shfl_xor_sync(0xffffffffu, qs, o);
            ks += __shfl_xor_sync(0xffffffffu, ks, o);
        }
        float qr = rsqrtf(qs + 1e-8f);
        float kr = rsqrtf(ks + 1e-8f);
        int row = row0 + r;
        ((float2*)(g_q + row*DD))[lane] = make_float2(q0*qr, q1*qr);
        ((float2*)(g_k + row*DD))[lane] = make_float2(k0*kr, k1*kr);
        ((float2*)(g_v + row*DD))[lane] = make_float2(v0 + bvv.x, v1 + bvv.y);
    }

    // ---- DFT magnitudes, bin = lane, packed twiddles ----
    u64 re2[4] = {0,0,0,0}, im2[4] = {0,0,0,0};
    const ulonglong2* Twp = (const ulonglong2*)g_twp;
    #pragma unroll 4
    for (int d2 = 0; d2 < 32; d2++) {
        ulonglong2 t2 = Twp[d2*32 + lane];    // (cos pair, sin pair)
        #pragma unroll
        for (int r = 0; r < 4; r++) {
            u64 h2 = ((const u64*)sh[warp][r])[d2];
            re2[r] = fma2(h2, t2.x, re2[r]);
            im2[r] = fma2(h2, t2.y, im2[r]);
        }
    }
    #pragma unroll
    for (int r = 0; r < 4; r++) {
        float2 rr = unp(re2[r]), ii = unp(im2[r]);
        float re = rr.x + rr.y, im = ii.x + ii.y;
        smag[warp][r][lane] = sqrtf(re*re + im*im);
    }
    __syncwarp();

    // ---- gate: 8 lanes per row, lane = (row, band) ----
    {
        int r   = lane >> 3;      // row within group of 4
        int bnd = lane & 7;       // band index
        const float* mg = smag[warp][r];
        float en = 0.25f * (mg[4*bnd] + mg[4*bnd+1] + mg[4*bnd+2] + mg[4*bnd+3]);
        float esum = en;
        esum += __shfl_xor_sync(0xffffffffu, esum, 1);
        esum += __shfl_xor_sync(0xffffffffu, esum, 2);
        esum += __shfl_xor_sync(0xffffffffu, esum, 4);
        float eni = en / fmaxf(esum, 1e-8f);
        float z0 = b1[2*bnd], z1 = b1[2*bnd+1];
        int gbase = lane & 24;    // start lane of this 8-lane group
        #pragma unroll
        for (int i = 0; i < 8; i++) {
            float ei = __shfl_sync(0xffffffffu, eni, gbase + i);
            z0 = fmaf(ei, W1[i*16 + 2*bnd],     z0);
            z1 = fmaf(ei, W1[i*16 + 2*bnd + 1], z1);
        }
        float s0 = z0 / (1.0f + expf(-z0)) * W2[2*bnd];
        float s1 = z1 / (1.0f + expf(-z1)) * W2[2*bnd+1];
        float hid = s0 + s1;
        hid += __shfl_xor_sync(0xffffffffu, hid, 1);
        hid += __shfl_xor_sync(0xffffffffu, hid, 2);
        hid += __shfl_xor_sync(0xffffffffu, hid, 4);
        if (bnd == 0) {
            float z2 = hid + b2[0];
            g_gam[row0 + r] = 0.5f + 0.49f / (1.0f + expf(-z2));
        }
    }
}

// ---------------- scan: 2 rows x 16 cols per thread (128-thread CTA) ----------------
// thread (rg, cg): rows {2rg, 2rg+1}, cols [cg*16, cg*16+16). k/q loads per thread
// unchanged vs 4-sub layout, but thread count halves -> L1 wavefronts ~0.45x.
// Reduction structure (4+4 u64 chains, shfl over 4 col-groups) bit-identical to R7.
__global__ void __launch_bounds__(128, 4) scan_kernel() {
    const int b  = blockIdx.x;
    const int cg = threadIdx.x & 3;        // col-group
    const int rg = threadIdx.x >> 2;       // row-group 0..31 (rows 2rg, 2rg+1)

    const ulonglong2* __restrict__ kp = (const ulonglong2*)(g_k + b*NN*DD + cg*16);
    const ulonglong2* __restrict__ qp = (const ulonglong2*)(g_q + b*NN*DD + cg*16);
    const float2* __restrict__ vp = (const float2*)(g_v + b*NN*DD) + rg;
    const float*  __restrict__ gp = g_gam + b*NN;
    float2*       __restrict__ op = (float2*)(g_o + b*NN*DD) + rg;

    u64 S0[8], S1[8];                      // rows 2rg and 2rg+1, 16 cols each
    #pragma unroll
    for (int i = 0; i < 8; i++) { S0[i] = 0ull; S1[i] = 0ull; }

    #pragma unroll 1
    for (int t = 0; t < NN; t++) {
        ulonglong2 kA = kp[0], kB = kp[1], kC = kp[2], kD = kp[3];
        ulonglong2 qA = qp[0], qB = qp[1], qC = qp[2], qD = qp[3];
        kp += 16; qp += 16;
        float gc  = *gp++;
        float2 vc = *vp; vp += 32;

        u64 k2[8] = {kA.x, kA.y, kB.x, kB.y, kC.x, kC.y, kD.x, kD.y};
        u64 q2[8] = {qA.x, qA.y, qB.x, qB.y, qC.x, qC.y, qD.x, qD.y};

        // pred per row: two 4-u64 chains (same grouping as R7), reduce over col-groups
        u64 pa0 = mul2(S0[0], k2[0]);
        pa0 = fma2(S0[1], k2[1], pa0);
        pa0 = fma2(S0[2], k2[2], pa0);
        pa0 = fma2(S0[3], k2[3], pa0);
        u64 pb0 = mul2(S0[4], k2[4]);
        pb0 = fma2(S0[5], k2[5], pb0);
        pb0 = fma2(S0[6], k2[6], pb0);
        pb0 = fma2(S0[7], k2[7], pb0);
        u64 pa1 = mul2(S1[0], k2[0]);
        pa1 = fma2(S1[1], k2[1], pa1);
        pa1 = fma2(S1[2], k2[2], pa1);
        pa1 = fma2(S1[3], k2[3], pa1);
        u64 pb1 = mul2(S1[4], k2[4]);
        pb1 = fma2(S1[5], k2[5], pb1);
        pb1 = fma2(S1[6], k2[6], pb1);
        pb1 = fma2(S1[7], k2[7], pb1);
        float2 ua0 = unp(pa0), ub0 = unp(pb0);
        float2 ua1 = unp(pa1), ub1 = unp(pb1);
        float pred0 = (ua0.x + ua0.y) + (ub0.x + ub0.y);
        float pred1 = (ua1.x + ua1.y) + (ub1.x + ub1.y);
        pred0 += __shfl_xor_sync(0xffffffffu, pred0, 1);
        pred1 += __shfl_xor_sync(0xffffffffu, pred1, 1);
        pred0 += __shfl_xor_sync(0xffffffffu, pred0, 2);
        pred1 += __shfl_xor_sync(0xffffffffu, pred1, 2);

        float d0 = fminf(fmaxf(vc.x - pred0, -5.0f), 5.0f);
        float d1 = fminf(fmaxf(vc.y - pred1, -5.0f), 5.0f);
        u64 g2  = dup2(gc);
        u64 dl0 = dup2(d0);
        u64 dl1 = dup2(d1);

        // update + o for both rows (packed)
        u64 oa0, ob0, oa1, ob1;
        S0[0] = upd2(S0[0], k2[0], g2, dl0);  oa0 = mul2(S0[0], q2[0]);
        S1[0] = upd2(S1[0], k2[0], g2, dl1);  oa1 = mul2(S1[0], q2[0]);
        S0[1] = upd2(S0[1], k2[1], g2, dl0);  oa0 = fma2(S0[1], q2[1], oa0);
        S1[1] = upd2(S1[1], k2[1], g2, dl1);  oa1 = fma2(S1[1], q2[1], oa1);
        S0[2] = upd2(S0[2], k2[2], g2, dl0);  oa0 = fma2(S0[2], q2[2], oa0);
        S1[2] = upd2(S1[2], k2[2], g2, dl1);  oa1 = fma2(S1[2], q2[2], oa1);
        S0[3] = upd2(S0[3], k2[3], g2, dl0);  oa0 = fma2(S0[3], q2[3], oa0);
        S1[3] = upd2(S1[3], k2[3], g2, dl1);  oa1 = fma2(S1[3], q2[3], oa1);
        S0[4] = upd2(S0[4], k2[4], g2, dl0);  ob0 = mul2(S0[4], q2[4]);
        S1[4] = upd2(S1[4], k2[4], g2, dl1);  ob1 = mul2(S1[4], q2[4]);
        S0[5] = upd2(S0[5], k2[5], g2, dl0);  ob0 = fma2(S0[5], q2[5], ob0);
        S1[5] = upd2(S1[5], k2[5], g2, dl1);  ob1 = fma2(S1[5], q2[5], ob1);
        S0[6] = upd2(S0[6], k2[6], g2, dl0);  ob0 = fma2(S0[6], q2[6], ob0);
        S1[6] = upd2(S1[6], k2[6], g2, dl1);  ob1 = fma2(S1[6], q2[6], ob1);
        S0[7] = upd2(S0[7], k2[7], g2, dl0);  ob0 = fma2(S0[7], q2[7], ob0);
        S1[7] = upd2(S1[7], k2[7], g2, dl1);  ob1 = fma2(S1[7], q2[7], ob1);

        float2 oa02 = unp(oa0), ob02 = unp(ob0);
        float2 oa12 = unp(oa1), ob12 = unp(ob1);
        float o0 = (oa02.x + oa02.y) + (ob02.x + ob02.y);
        float o1 = (oa12.x + oa12.y) + (ob12.x + ob12.y);
        o0 += __shfl_xor_sync(0xffffffffu, o0, 1);
        o1 += __shfl_xor_sync(0xffffffffu, o1, 1);
        o0 += __shfl_xor_sync(0xffffffffu, o0, 2);
        o1 += __shfl_xor_sync(0xffffffffu, o1, 2);
        if (cg == 0) op[t*32] = make_float2(o0, o1);
    }
}

// ---------------- epilogue: 4 rows/warp ----------------
__global__ void __launch_bounds__(256) post_kernel(
    const float* __restrict__ x, const float* __restrict__ g_post,
    const float* __restrict__ bo, float* __restrict__ out)
{
    const int warp = threadIdx.x >> 5;
    const int lane = threadIdx.x & 31;
    const int row0 = blockIdx.x * 32 + warp * 4;
    __shared__ __align__(16) float sh[8][4][DD];

    float2 gp2 = ((const float2*)g_post)[lane];
    #pragma unroll
    for (int r = 0; r < 4; r++) {
        float2 ov = ((const float2*)(g_o + (row0 + r)*DD))[lane];
        float s  = ov.x + ov.y;
        float ss = ov.x*ov.x + ov.y*ov.y;
        #pragma unroll
        for (int o = 16; o; o >>= 1) {
            s  += __shfl_xor_sync(0xffffffffu, s,  o);
            ss += __shfl_xor_sync(0xffffffffu, ss, o);
        }
        float mean = s * (1.0f/64.0f);
        float var  = fmaf(-mean, mean, ss * (1.0f/64.0f));
        float rn = rsqrtf(var + 1e-8f);
        sh[warp][r][2*lane]   = (ov.x - mean) * rn * gp2.x;
        sh[warp][r][2*lane+1] = (ov.y - mean) * rn * gp2.y;
    }
    __syncwarp();

    u64 aE[4], aO[4];
    #pragma unroll
    for (int r = 0; r < 4; r++) { aE[r] = aO[r] = 0ull; }
    const ulonglong2* Wop = (const ulonglong2*)g_Wop;
    #pragma unroll 4
    for (int e2 = 0; e2 < 32; e2++) {
        ulonglong2 wo = Wop[e2*32 + lane];
        #pragma unroll
        for (int r = 0; r < 4; r++) {
            u64 h2 = ((const u64*)sh[warp][r])[e2];
            aE[r] = fma2(h2, wo.x, aE[r]);
            aO[r] = fma2(h2, wo.y, aO[r]);
        }
    }
    float2 bov = ((const float2*)bo)[lane];
    #pragma unroll
    for (int r = 0; r < 4; r++) {
        float2 e0 = unp(aE[r]), e1 = unp(aO[r]);
        int row = row0 + r;
        float2 xv = ((const float2*)(x + row*DD))[lane];
        ((float2*)(out + row*DD))[lane] =
            make_float2(xv.x + e0.x + e0.y + bov.x,
                        xv.y + e1.x + e1.y + bov.y);
    }
}

// ---------------- launch ----------------
extern "C" void kernel_launch(void* const* d_in, const int* in_sizes, int n_in,
                              void* d_out, int out_size)
{
    const float* x      = (const float*)d_in[0];
    const float* g_norm = (const float*)d_in[1];
    const float* Wq     = (const float*)d_in[2];
    const float* Wk     = (const float*)d_in[3];
    const float* Wv     = (const float*)d_in[4];
    const float* bv     = (const float*)d_in[5];
    const float* Wo     = (const float*)d_in[6];
    const float* bo     = (const float*)d_in[7];
    const float* g_post = (const float*)d_in[8];
    const float* W1     = (const float*)d_in[9];
    const float* b1     = (const float*)d_in[10];
    const float* W2     = (const float*)d_in[11];
    const float* b2     = (const float*)d_in[12];
    float* out          = (float*)d_out;

    init_kernel<<<20, 256>>>(Wq, Wk, Wv, Wo);
    pre_kernel<<<ROWS/32, 256>>>(x, g_norm, bv, W1, b1, W2, b2);
    scan_kernel<<<BB, 128>>>();
    post_kernel<<<ROWS/32, 256>>>(x, g_post, bo, out);
}

// round 15
// speedup vs baseline: 1.9447x; 1.0145x over previous
#include <cuda_runtime.h>
#include <math.h>

#define BB 512
#define NN 120
#define DD 64
#define ROWS (BB*NN)           // 61440
#define NBINS 32

typedef unsigned long long u64;

// ---------------- scratch (static device arrays; no cudaMalloc) ----------------
__device__ float  g_q[ROWS*DD];
__device__ float  g_k[ROWS*DD];
__device__ float  g_v[ROWS*DD];
__device__ float  g_gam[ROWS];
__device__ float  g_o[ROWS*DD];
// packed twiddles: twp[d2*32+f] = (cos(w*f*2d2), cos(w*f*(2d2+1)), sin(...), sin(...))
__device__ float4 g_twp[1024];
// W repacked over e-pairs: P[e2*32+lane] = (W[2e2][2l], W[2e2+1][2l], W[2e2][2l+1], W[2e2+1][2l+1])
__device__ float4 g_Wqp[1024], g_Wkp[1024], g_Wvp[1024], g_Wop[1024];

// ---------------- f32x2 helpers ----------------
__device__ __forceinline__ u64 fma2(u64 a, u64 b, u64 c) {
    u64 d; asm("fma.rn.f32x2 %0,%1,%2,%3;" : "=l"(d) : "l"(a), "l"(b), "l"(c)); return d;
}
__device__ __forceinline__ u64 mul2(u64 a, u64 b) {
    u64 d; asm("mul.rn.f32x2 %0,%1,%2;" : "=l"(d) : "l"(a), "l"(b)); return d;
}
__device__ __forceinline__ u64 dup2(float v) {
    u64 r; asm("mov.b64 %0,{%1,%1};" : "=l"(r) : "f"(v)); return r;
}
__device__ __forceinline__ float2 unp(u64 v) {
    float a, b; asm("mov.b64 {%0,%1},%2;" : "=f"(a), "=f"(b) : "l"(v));
    return make_float2(a, b);
}
// S' = clip(g*S + delta*k, +-10)
__device__ __forceinline__ u64 upd2(u64 S, u64 k, u64 g, u64 delta) {
    u64 r;
    asm("{\n\t"
        ".reg .f32 lo,hi;\n\t"
        ".reg .b64 t;\n\t"
        "mul.rn.f32x2 t, %2, %3;\n\t"
        "fma.rn.f32x2 t, %4, %1, t;\n\t"
        "mov.b64 {lo,hi}, t;\n\t"
        "min.f32 lo, lo, 0f41200000;\n\t"
        "max.f32 lo, lo, 0fC1200000;\n\t"
        "min.f32 hi, hi, 0f41200000;\n\t"
        "max.f32 hi, hi, 0fC1200000;\n\t"
        "mov.b64 %0, {lo,hi};\n\t"
        "}"
        : "=l"(r) : "l"(S), "l"(k), "l"(delta), "l"(g));
    return r;
}

// ---------------- init: packed twiddles + W e-pair repack ----------------
__global__ void init_kernel(const float* __restrict__ Wq, const float* __restrict__ Wk,
                            const float* __restrict__ Wv, const float* __restrict__ Wo) {
    int i = blockIdx.x * blockDim.x + threadIdx.x;
    if (i < 1024) {
        int d2 = i >> 5, f = i & 31;
        int m0 = (f * (2*d2))     & 63;       // exact modular angle reduction
        int m1 = (f * (2*d2 + 1)) & 63;
        const double w = 2.0 * 3.14159265358979323846 / 64.0;
        g_twp[i] = make_float4((float)cos(w*m0), (float)cos(w*m1),
                               (float)sin(w*m0), (float)sin(w*m1));
    } else if (i < 5120) {
        int s = (i - 1024) >> 10, j = (i - 1024) & 1023;
        int e2 = j >> 5, l = j & 31;
        const float* W = (s == 0) ? Wq : (s == 1) ? Wk : (s == 2) ? Wv : Wo;
        float4*      P = (s == 0) ? g_Wqp : (s == 1) ? g_Wkp : (s == 2) ? g_Wvp : g_Wop;
        int a = (2*e2)*DD + 2*l;
        P[j] = make_float4(W[a], W[a+DD], W[a+1], W[a+DD+1]);
    }
}

// ---------------- preprocess: 4 rows/warp, combined q/k/v pass ----------------
__global__ void __launch_bounds__(256) pre_kernel(
    const float* __restrict__ x,  const float* __restrict__ g_norm,
    const float* __restrict__ bv,
    const float* __restrict__ W1, const float* __restrict__ b1,
    const float* __restrict__ W2, const float* __restrict__ b2)
{
    const int warp = threadIdx.x >> 5;
    const int lane = threadIdx.x & 31;
    const int row0 = blockIdx.x * 32 + warp * 4;
    __shared__ __align__(16) float sh[8][4][DD];
    __shared__ float smag[8][4][NBINS];

    // ---- zc_rms for 4 rows (variance identity; parallel reductions) ----
    float2 gv = ((const float2*)g_norm)[lane];
    #pragma unroll
    for (int r = 0; r < 4; r++) {
        float2 xv = ((const float2*)(x + (row0 + r)*DD))[lane];
        float s  = xv.x + xv.y;
        float ss = xv.x*xv.x + xv.y*xv.y;
        #pragma unroll
        for (int o = 16; o; o >>= 1) {
            s  += __shfl_xor_sync(0xffffffffu, s,  o);
            ss += __shfl_xor_sync(0xffffffffu, ss, o);
        }
        float mean = s * (1.0f/64.0f);
        float var  = fmaf(-mean, mean, ss * (1.0f/64.0f));
        float rn = rsqrtf(var + 1e-8f);
        sh[warp][r][2*lane]   = (xv.x - mean) * rn * gv.x;
        sh[warp][r][2*lane+1] = (xv.y - mean) * rn * gv.y;
    }
    __syncwarp();

    // ---- three matvecs, packed over e-pairs, one combined pass ----
    u64 qE[4], qO[4], kE[4], kO[4], vE[4], vO[4];
    #pragma unroll
    for (int r = 0; r < 4; r++) { qE[r]=qO[r]=kE[r]=kO[r]=vE[r]=vO[r]=0ull; }
    const ulonglong2* Wqp = (const ulonglong2*)g_Wqp;
    const ulonglong2* Wkp = (const ulonglong2*)g_Wkp;
    const ulonglong2* Wvp = (const ulonglong2*)g_Wvp;
    #pragma unroll 4
    for (int e2 = 0; e2 < 32; e2++) {
        ulonglong2 wq = Wqp[e2*32 + lane];
        ulonglong2 wk = Wkp[e2*32 + lane];
        ulonglong2 wv = Wvp[e2*32 + lane];
        #pragma unroll
        for (int r = 0; r < 4; r++) {
            u64 h2 = ((const u64*)sh[warp][r])[e2];   // (h[2e2], h[2e2+1])
            qE[r] = fma2(h2, wq.x, qE[r]);  qO[r] = fma2(h2, wq.y, qO[r]);
            kE[r] = fma2(h2, wk.x, kE[r]);  kO[r] = fma2(h2, wk.y, kO[r]);
            vE[r] = fma2(h2, wv.x, vE[r]);  vO[r] = fma2(h2, wv.y, vO[r]);
        }
    }
    float2 bvv = ((const float2*)bv)[lane];
    #pragma unroll
    for (int r = 0; r < 4; r++) {
        float2 e0 = unp(qE[r]), e1 = unp(qO[r]);
        float q0 = e0.x + e0.y, q1 = e1.x + e1.y;
        e0 = unp(kE[r]); e1 = unp(kO[r]);
        float k0 = e0.x + e0.y, k1 = e1.x + e1.y;
        e0 = unp(vE[r]); e1 = unp(vO[r]);
        float v0 = e0.x + e0.y, v1 = e1.x + e1.y;

        float qs = q0*q0 + q1*q1;
        float ks = k0*k0 + k1*k1;
        #pragma unroll
        for (int o = 16; o; o >>= 1) {
            qs += __shfl_xor_sync(0xffffffffu, qs, o);
            ks += __shfl_xor_sync(0xffffffffu, ks, o);
        }
        float qr = rsqrtf(qs + 1e-8f);
        float kr = rsqrtf(ks + 1e-8f);
        int row = row0 + r;
        ((float2*)(g_q + row*DD))[lane] = make_float2(q0*qr, q1*qr);
        ((float2*)(g_k + row*DD))[lane] = make_float2(k0*kr, k1*kr);
        ((float2*)(g_v + row*DD))[lane] = make_float2(v0 + bvv.x, v1 + bvv.y);
    }

    // ---- DFT magnitudes, bin = lane, packed twiddles ----
    u64 re2[4] = {0,0,0,0}, im2[4] = {0,0,0,0};
    const ulonglong2* Twp = (const ulonglong2*)g_twp;
    #pragma unroll 4
    for (int d2 = 0; d2 < 32; d2++) {
        ulonglong2 t2 = Twp[d2*32 + lane];    // (cos pair, sin pair)
        #pragma unroll
        for (int r = 0; r < 4; r++) {
            u64 h2 = ((const u64*)sh[warp][r])[d2];
            re2[r] = fma2(h2, t2.x, re2[r]);
            im2[r] = fma2(h2, t2.y, im2[r]);
        }
    }
    #pragma unroll
    for (int r = 0; r < 4; r++) {
        float2 rr = unp(re2[r]), ii = unp(im2[r]);
        float re = rr.x + rr.y, im = ii.x + ii.y;
        smag[warp][r][lane] = sqrtf(re*re + im*im);
    }
    __syncwarp();

    // ---- gate: 8 lanes per row, lane = (row, band) ----
    {
        int r   = lane >> 3;      // row within group of 4
        int bnd = lane & 7;       // band index
        const float* mg = smag[warp][r];
        float en = 0.25f * (mg[4*bnd] + mg[4*bnd+1] + mg[4*bnd+2] + mg[4*bnd+3]);
        float esum = en;
        esum += __shfl_xor_sync(0xffffffffu, esum, 1);
        esum += __shfl_xor_sync(0xffffffffu, esum, 2);
        esum += __shfl_xor_sync(0xffffffffu, esum, 4);
        float eni = en / fmaxf(esum, 1e-8f);
        float z0 = b1[2*bnd], z1 = b1[2*bnd+1];
        int gbase = lane & 24;    // start lane of this 8-lane group
        #pragma unroll
        for (int i = 0; i < 8; i++) {
            float ei = __shfl_sync(0xffffffffu, eni, gbase + i);
            z0 = fmaf(ei, W1[i*16 + 2*bnd],     z0);
            z1 = fmaf(ei, W1[i*16 + 2*bnd + 1], z1);
        }
        float s0 = z0 / (1.0f + expf(-z0)) * W2[2*bnd];
        float s1 = z1 / (1.0f + expf(-z1)) * W2[2*bnd+1];
        float hid = s0 + s1;
        hid += __shfl_xor_sync(0xffffffffu, hid, 1);
        hid += __shfl_xor_sync(0xffffffffu, hid, 2);
        hid += __shfl_xor_sync(0xffffffffu, hid, 4);
        if (bnd == 0) {
            float z2 = hid + b2[0];
            g_gam[row0 + r] = 0.5f + 0.49f / (1.0f + expf(-z2));
        }
    }
}

// ---------------- scan: 2 rows x 16 INTERLEAVED cols per thread ----------------
// thread (rg, cg): rows {2rg, 2rg+1}, cols {chunk*16 + cg*4 + j : chunk 0..3, j 0..3}.
// Per-warp LDG.128 now covers a contiguous 64B half-line (cg stride 16B) -> 1 L1
// wavefront per load instead of 2. Partition of the 64-col dot product is
// permutation-invariant (only fp association changes).
__global__ void __launch_bounds__(128, 4) scan_kernel() {
    const int b  = blockIdx.x;
    const int cg = threadIdx.x & 3;        // col-group (stride-4 interleave)
    const int rg = threadIdx.x >> 2;       // row-group 0..31 (rows 2rg, 2rg+1)

    // base at cg*4 floats; chunks at +16 floats (= +4 ulonglong2)
    const ulonglong2* __restrict__ kp = (const ulonglong2*)(g_k + b*NN*DD + cg*4);
    const ulonglong2* __restrict__ qp = (const ulonglong2*)(g_q + b*NN*DD + cg*4);
    const float2* __restrict__ vp = (const float2*)(g_v + b*NN*DD) + rg;
    const float*  __restrict__ gp = g_gam + b*NN;
    float2*       __restrict__ op = (float2*)(g_o + b*NN*DD) + rg;

    u64 S0[8], S1[8];                      // rows 2rg and 2rg+1, 16 interleaved cols
    #pragma unroll
    for (int i = 0; i < 8; i++) { S0[i] = 0ull; S1[i] = 0ull; }

    #pragma unroll 1
    for (int t = 0; t < NN; t++) {
        ulonglong2 kA = kp[0], kB = kp[4], kC = kp[8], kD = kp[12];
        ulonglong2 qA = qp[0], qB = qp[4], qC = qp[8], qD = qp[12];
        kp += 16; qp += 16;
        float gc  = *gp++;
        float2 vc = *vp; vp += 32;

        u64 k2[8] = {kA.x, kA.y, kB.x, kB.y, kC.x, kC.y, kD.x, kD.y};
        u64 q2[8] = {qA.x, qA.y, qB.x, qB.y, qC.x, qC.y, qD.x, qD.y};

        // pred per row: two 4-u64 chains, reduce over col-groups
        u64 pa0 = mul2(S0[0], k2[0]);
        pa0 = fma2(S0[1], k2[1], pa0);
        pa0 = fma2(S0[2], k2[2], pa0);
        pa0 = fma2(S0[3], k2[3], pa0);
        u64 pb0 = mul2(S0[4], k2[4]);
        pb0 = fma2(S0[5], k2[5], pb0);
        pb0 = fma2(S0[6], k2[6], pb0);
        pb0 = fma2(S0[7], k2[7], pb0);
        u64 pa1 = mul2(S1[0], k2[0]);
        pa1 = fma2(S1[1], k2[1], pa1);
        pa1 = fma2(S1[2], k2[2], pa1);
        pa1 = fma2(S1[3], k2[3], pa1);
        u64 pb1 = mul2(S1[4], k2[4]);
        pb1 = fma2(S1[5], k2[5], pb1);
        pb1 = fma2(S1[6], k2[6], pb1);
        pb1 = fma2(S1[7], k2[7], pb1);
        float2 ua0 = unp(pa0), ub0 = unp(pb0);
        float2 ua1 = unp(pa1), ub1 = unp(pb1);
        float pred0 = (ua0.x + ua0.y) + (ub0.x + ub0.y);
        float pred1 = (ua1.x + ua1.y) + (ub1.x + ub1.y);
        pred0 += __shfl_xor_sync(0xffffffffu, pred0, 1);
        pred1 += __shfl_xor_sync(0xffffffffu, pred1, 1);
        pred0 += __shfl_xor_sync(0xffffffffu, pred0, 2);
        pred1 += __shfl_xor_sync(0xffffffffu, pred1, 2);

        float d0 = fminf(fmaxf(vc.x - pred0, -5.0f), 5.0f);
        float d1 = fminf(fmaxf(vc.y - pred1, -5.0f), 5.0f);
        u64 g2  = dup2(gc);
        u64 dl0 = dup2(d0);
        u64 dl1 = dup2(d1);

        // update + o for both rows (packed)
        u64 oa0, ob0, oa1, ob1;
        S0[0] = upd2(S0[0], k2[0], g2, dl0);  oa0 = mul2(S0[0], q2[0]);
        S1[0] = upd2(S1[0], k2[0], g2, dl1);  oa1 = mul2(S1[0], q2[0]);
        S0[1] = upd2(S0[1], k2[1], g2, dl0);  oa0 = fma2(S0[1], q2[1], oa0);
        S1[1] = upd2(S1[1], k2[1], g2, dl1);  oa1 = fma2(S1[1], q2[1], oa1);
        S0[2] = upd2(S0[2], k2[2], g2, dl0);  oa0 = fma2(S0[2], q2[2], oa0);
        S1[2] = upd2(S1[2], k2[2], g2, dl1);  oa1 = fma2(S1[2], q2[2], oa1);
        S0[3] = upd2(S0[3], k2[3], g2, dl0);  oa0 = fma2(S0[3], q2[3], oa0);
        S1[3] = upd2(S1[3], k2[3], g2, dl1);  oa1 = fma2(S1[3], q2[3], oa1);
        S0[4] = upd2(S0[4], k2[4], g2, dl0);  ob0 = mul2(S0[4], q2[4]);
        S1[4] = upd2(S1[4], k2[4], g2, dl1);  ob1 = mul2(S1[4], q2[4]);
        S0[5] = upd2(S0[5], k2[5], g2, dl0);  ob0 = fma2(S0[5], q2[5], ob0);
        S1[5] = upd2(S1[5], k2[5], g2, dl1);  ob1 = fma2(S1[5], q2[5], ob1);
        S0[6] = upd2(S0[6], k2[6], g2, dl0);  ob0 = fma2(S0[6], q2[6], ob0);
        S1[6] = upd2(S1[6], k2[6], g2, dl1);  ob1 = fma2(S1[6], q2[6], ob1);
        S0[7] = upd2(S0[7], k2[7], g2, dl0);  ob0 = fma2(S0[7], q2[7], ob0);
        S1[7] = upd2(S1[7], k2[7], g2, dl1);  ob1 = fma2(S1[7], q2[7], ob1);

        float2 oa02 = unp(oa0), ob02 = unp(ob0);
        float2 oa12 = unp(oa1), ob12 = unp(ob1);
        float o0 = (oa02.x + oa02.y) + (ob02.x + ob02.y);
        float o1 = (oa12.x + oa12.y) + (ob12.x + ob12.y);
        o0 += __shfl_xor_sync(0xffffffffu, o0, 1);
        o1 += __shfl_xor_sync(0xffffffffu, o1, 1);
        o0 += __shfl_xor_sync(0xffffffffu, o0, 2);
        o1 += __shfl_xor_sync(0xffffffffu, o1, 2);
        if (cg == 0) op[t*32] = make_float2(o0, o1);
    }
}

// ---------------- epilogue: 4 rows/warp ----------------
__global__ void __launch_bounds__(256) post_kernel(
    const float* __restrict__ x, const float* __restrict__ g_post,
    const float* __restrict__ bo, float* __restrict__ out)
{
    const int warp = threadIdx.x >> 5;
    const int lane = threadIdx.x & 31;
    const int row0 = blockIdx.x * 32 + warp * 4;
    __shared__ __align__(16) float sh[8][4][DD];

    float2 gp2 = ((const float2*)g_post)[lane];
    #pragma unroll
    for (int r = 0; r < 4; r++) {
        float2 ov = ((const float2*)(g_o + (row0 + r)*DD))[lane];
        float s  = ov.x + ov.y;
        float ss = ov.x*ov.x + ov.y*ov.y;
        #pragma unroll
        for (int o = 16; o; o >>= 1) {
            s  += __shfl_xor_sync(0xffffffffu, s,  o);
            ss += __shfl_xor_sync(0xffffffffu, ss, o);
        }
        float mean = s * (1.0f/64.0f);
        float var  = fmaf(-mean, mean, ss * (1.0f/64.0f));
        float rn = rsqrtf(var + 1e-8f);
        sh[warp][r][2*lane]   = (ov.x - mean) * rn * gp2.x;
        sh[warp][r][2*lane+1] = (ov.y - mean) * rn * gp2.y;
    }
    __syncwarp();

    u64 aE[4], aO[4];
    #pragma unroll
    for (int r = 0; r < 4; r++) { aE[r] = aO[r] = 0ull; }
    const ulonglong2* Wop = (const ulonglong2*)g_Wop;
    #pragma unroll 4
    for (int e2 = 0; e2 < 32; e2++) {
        ulonglong2 wo = Wop[e2*32 + lane];
        #pragma unroll
        for (int r = 0; r < 4; r++) {
            u64 h2 = ((const u64*)sh[warp][r])[e2];
            aE[r] = fma2(h2, wo.x, aE[r]);
            aO[r] = fma2(h2, wo.y, aO[r]);
        }
    }
    float2 bov = ((const float2*)bo)[lane];
    #pragma unroll
    for (int r = 0; r < 4; r++) {
        float2 e0 = unp(aE[r]), e1 = unp(aO[r]);
        int row = row0 + r;
        float2 xv = ((const float2*)(x + row*DD))[lane];
        ((float2*)(out + row*DD))[lane] =
            make_float2(xv.x + e0.x + e0.y + bov.x,
                        xv.y + e1.x + e1.y + bov.y);
    }
}

// ---------------- launch ----------------
extern "C" void kernel_launch(void* const* d_in, const int* in_sizes, int n_in,
                              void* d_out, int out_size)
{
    const float* x      = (const float*)d_in[0];
    const float* g_norm = (const float*)d_in[1];
    const float* Wq     = (const float*)d_in[2];
    const float* Wk     = (const float*)d_in[3];
    const float* Wv     = (const float*)d_in[4];
    const float* bv     = (const float*)d_in[5];
    const float* Wo     = (const float*)d_in[6];
    const float* bo     = (const float*)d_in[7];
    const float* g_post = (const float*)d_in[8];
    const float* W1     = (const float*)d_in[9];
    const float* b1     = (const float*)d_in[10];
    const float* W2     = (const float*)d_in[11];
    const float* b2     = (const float*)d_in[12];
    float* out          = (float*)d_out;

    init_kernel<<<20, 256>>>(Wq, Wk, Wv, Wo);
    pre_kernel<<<ROWS/32, 256>>>(x, g_norm, bv, W1, b1, W2, b2);
    scan_kernel<<<BB, 128>>>();
    post_kernel<<<ROWS/32, 256>>>(x, g_post, bo, out);
}